// round 7
// baseline (speedup 1.0000x reference)
#include <cuda_runtime.h>

namespace {

constexpr int T = 2048;
constexpr int B = 4096;
constexpr int BLK = 128;   // 8192 threads -> 64 blocks x 4 warps = 1 warp/SMSP

typedef unsigned long long u64;

__device__ __forceinline__ u64 pack2(float lo, float hi) {
    u64 r; asm("mov.b64 %0,{%1,%2};" : "=l"(r) : "f"(lo), "f"(hi)); return r;
}
__device__ __forceinline__ void unpack2(u64 v, float& lo, float& hi) {
    asm("mov.b64 {%0,%1},%2;" : "=f"(lo), "=f"(hi) : "l"(v));
}
__device__ __forceinline__ u64 ffma2(u64 a, u64 b, u64 c) {
    u64 d; asm("fma.rn.f32x2 %0,%1,%2,%3;" : "=l"(d) : "l"(a), "l"(b), "l"(c)); return d;
}
__device__ __forceinline__ u64 fmul2(u64 a, u64 b) {
    u64 d; asm("mul.rn.f32x2 %0,%1,%2;" : "=l"(d) : "l"(a), "l"(b)); return d;
}
__device__ __forceinline__ float tanha(float x) {
    float y; asm("tanh.approx.f32 %0,%1;" : "=f"(y) : "f"(x)); return y;
}
__device__ __forceinline__ float hadd(u64 v) {
    float lo, hi; unpack2(v, lo, hi); return lo + hi;
}

// TWO chains per thread. Thread q of group g runs chains c0=2g and c0+1 with
// ONE shared register set of weights. The chains are independent dependency
// graphs, so every MUFU/SHFL/FFMA stall of one chain is filled by the other
// chain's instructions inside the same warp (in-thread ILP instead of relying
// on sibling-warp interleave, which R6 showed stalls in lockstep).
// Per chain, thread q owns h-units {q, q+4}; weight slots rotated so slot 0
// is the locally-held pair and only 3 foreign pairs arrive via 64-bit shfl.
// Activations via MUFU.TANH with 1/2 folded into the r/z weights.
__global__ void __launch_bounds__(BLK, 1) gru_fused_kernel(
    const float* __restrict__ x,
    const float* __restrict__ W_ih,
    const float* __restrict__ W_hh,
    const float* __restrict__ b_ih,
    const float* __restrict__ b_hh,
    const float* __restrict__ W_fc,
    const float* __restrict__ b_fc,
    float* __restrict__ out)
{
    const int tid = blockIdx.x * BLK + threadIdx.x;
    const int g = tid >> 2;          // chain-pair index 0..2047
    const int q = tid & 3;
    const int c0 = g * 2;

    const float HS = 0.5f;           // tanh-sigmoid pre-scale

    // ---- shared register-resident weights (identical for both chains) ----
    u64 Wr[2][4], Wz[2][4], Wn[2][4];   // [row A/B][slot k], k -> j=(q+k)&3
    u64 Xr[2][2], Xz[2][2], Xn[2][2];
    u64 Br[2], Bz[2], Bnx[2], Bnh[2];
#pragma unroll
    for (int rr = 0; rr < 2; rr++) {
        const int gr = q + 4 * rr;
        const int gz = 8 + q + 4 * rr;
        const int gn = 16 + q + 4 * rr;
#pragma unroll
        for (int k = 0; k < 4; k++) {
            const int j = (q + k) & 3;
            Wr[rr][k] = pack2(HS * W_hh[gr * 8 + j], HS * W_hh[gr * 8 + j + 4]);
            Wz[rr][k] = pack2(HS * W_hh[gz * 8 + j], HS * W_hh[gz * 8 + j + 4]);
            Wn[rr][k] = pack2(W_hh[gn * 8 + j], W_hh[gn * 8 + j + 4]);
        }
        Xr[rr][0] = pack2(HS * W_ih[gr * 4 + 0], HS * W_ih[gr * 4 + 2]);
        Xr[rr][1] = pack2(HS * W_ih[gr * 4 + 1], HS * W_ih[gr * 4 + 3]);
        Xz[rr][0] = pack2(HS * W_ih[gz * 4 + 0], HS * W_ih[gz * 4 + 2]);
        Xz[rr][1] = pack2(HS * W_ih[gz * 4 + 1], HS * W_ih[gz * 4 + 3]);
        Xn[rr][0] = pack2(W_ih[gn * 4 + 0], W_ih[gn * 4 + 2]);
        Xn[rr][1] = pack2(W_ih[gn * 4 + 1], W_ih[gn * 4 + 3]);
        Br[rr]  = pack2(HS * (b_ih[gr] + b_hh[gr]), 0.0f);
        Bz[rr]  = pack2(HS * (b_ih[gz] + b_hh[gz]), 0.0f);
        Bnx[rr] = pack2(b_ih[gn], 0.0f);
        Bnh[rr] = pack2(b_hh[gn], 0.0f);
    }
    u64 Wf[4];
#pragma unroll
    for (int k = 0; k < 4; k++) {
        const int j = (q + k) & 3;
        Wf[k] = pack2(W_fc[q * 8 + j], W_fc[q * 8 + j + 4]);
    }
    const u64 bfp = pack2(b_fc[q], 0.0f);

    const int j1 = (q + 1) & 3, j2 = (q + 2) & 3, j3 = (q + 3) & 3;

    // ---- per-chain state ----
    const float4* xp[2];
    float* op[2];
#pragma unroll
    for (int c = 0; c < 2; c++) {
        xp[c] = reinterpret_cast<const float4*>(x) + (size_t)(c0 + c) * T;
        op[c] = out + (size_t)(c0 + c) * T * 4 + q;
    }
    float hA[2] = {0.0f, 0.0f}, hB[2] = {0.0f, 0.0f};
    u64 p0[2] = {0, 0}, p1[2] = {0, 0}, p2[2] = {0, 0}, p3[2] = {0, 0};

    // 3-deep x prefetch pipeline per chain
    float4 xb0[2], xb1[2], xb2[2];
#pragma unroll
    for (int c = 0; c < 2; c++) { xb0[c] = xp[c][0]; xb1[c] = xp[c][1]; xb2[c] = xp[c][2]; }

#pragma unroll 2
    for (int t = 0; t < T; t++) {
        int tn = t + 3; tn = (tn < T) ? tn : (T - 1);   // shared across chains
        const int tp = t - (t > 0);

        float4 xc[2];
#pragma unroll
        for (int c = 0; c < 2; c++) {
            xc[c] = xb0[c]; xb0[c] = xb1[c]; xb1[c] = xb2[c];
            xb2[c] = xp[c][tn];
        }

        // ---- emit y_{t-1} (dummy at t==0, overwritten at t==1) ----
#pragma unroll
        for (int c = 0; c < 2; c++) {
            u64 ya = ffma2(Wf[0], p0[c], ffma2(Wf[1], p1[c], bfp));
            u64 yb = ffma2(Wf[2], p2[c], fmul2(Wf[3], p3[c]));
            float yl, yh, yl2, yh2;
            unpack2(ya, yl, yh); unpack2(yb, yl2, yh2);
            op[c][tp * 4] = (yl + yh) + (yl2 + yh2);
        }

        // ---- gate accumulators, both chains interleaved by the scheduler ----
        u64 aR[2][2], aZ[2][2], aNX[2][2], aNH[2][2];
#pragma unroll
        for (int c = 0; c < 2; c++) {
            const u64 xq0 = pack2(xc[c].x, xc[c].z);
            const u64 xq1 = pack2(xc[c].y, xc[c].w);
#pragma unroll
            for (int rr = 0; rr < 2; rr++) {
                aR[c][rr]  = ffma2(Xr[rr][1], xq1, ffma2(Xr[rr][0], xq0, Br[rr]));
                aZ[c][rr]  = ffma2(Xz[rr][1], xq1, ffma2(Xz[rr][0], xq0, Bz[rr]));
                aNX[c][rr] = ffma2(Xn[rr][1], xq1, ffma2(Xn[rr][0], xq0, Bnx[rr]));
                aNH[c][rr] = Bnh[rr];
            }
#pragma unroll
            for (int rr = 0; rr < 2; rr++) {
                aR[c][rr]  = ffma2(Wr[rr][0], p0[c], aR[c][rr]);
                aR[c][rr]  = ffma2(Wr[rr][1], p1[c], aR[c][rr]);
                aR[c][rr]  = ffma2(Wr[rr][2], p2[c], aR[c][rr]);
                aR[c][rr]  = ffma2(Wr[rr][3], p3[c], aR[c][rr]);
                aZ[c][rr]  = ffma2(Wz[rr][0], p0[c], aZ[c][rr]);
                aZ[c][rr]  = ffma2(Wz[rr][1], p1[c], aZ[c][rr]);
                aZ[c][rr]  = ffma2(Wz[rr][2], p2[c], aZ[c][rr]);
                aZ[c][rr]  = ffma2(Wz[rr][3], p3[c], aZ[c][rr]);
                aNH[c][rr] = ffma2(Wn[rr][0], p0[c], aNH[c][rr]);
                aNH[c][rr] = ffma2(Wn[rr][1], p1[c], aNH[c][rr]);
                aNH[c][rr] = ffma2(Wn[rr][2], p2[c], aNH[c][rr]);
                aNH[c][rr] = ffma2(Wn[rr][3], p3[c], aNH[c][rr]);
            }
        }

        // ---- activations + h update + exchange ----
#pragma unroll
        for (int c = 0; c < 2; c++) {
            const float rA = fmaf(0.5f, tanha(hadd(aR[c][0])), 0.5f);
            const float rB = fmaf(0.5f, tanha(hadd(aR[c][1])), 0.5f);
            const float zA = fmaf(0.5f, tanha(hadd(aZ[c][0])), 0.5f);
            const float zB = fmaf(0.5f, tanha(hadd(aZ[c][1])), 0.5f);

            const float vA = fmaf(rA, hadd(aNH[c][0]), hadd(aNX[c][0]));
            const float vB = fmaf(rB, hadd(aNH[c][1]), hadd(aNX[c][1]));
            const float nA = tanha(vA);
            const float nB = tanha(vB);

            hA[c] = fmaf(zA, hA[c] - nA, nA);
            hB[c] = fmaf(zB, hB[c] - nB, nB);

            p0[c] = pack2(hA[c], hB[c]);
            double hd = __longlong_as_double((long long)p0[c]);
            p1[c] = (u64)__double_as_longlong(__shfl_sync(0xffffffffu, hd, j1, 4));
            p2[c] = (u64)__double_as_longlong(__shfl_sync(0xffffffffu, hd, j2, 4));
            p3[c] = (u64)__double_as_longlong(__shfl_sync(0xffffffffu, hd, j3, 4));
        }
    }

    // ---- final y_{T-1} ----
#pragma unroll
    for (int c = 0; c < 2; c++) {
        u64 ya = ffma2(Wf[0], p0[c], ffma2(Wf[1], p1[c], bfp));
        u64 yb = ffma2(Wf[2], p2[c], fmul2(Wf[3], p3[c]));
        float yl, yh, yl2, yh2;
        unpack2(ya, yl, yh); unpack2(yb, yl2, yh2);
        op[c][(T - 1) * 4] = (yl + yh) + (yl2 + yh2);
    }
}

} // namespace

extern "C" void kernel_launch(void* const* d_in, const int* in_sizes, int n_in,
                              void* d_out, int out_size)
{
    const float* x    = (const float*)d_in[0];
    const float* W_ih = (const float*)d_in[1];
    const float* W_hh = (const float*)d_in[2];
    const float* b_ih = (const float*)d_in[3];
    const float* b_hh = (const float*)d_in[4];
    const float* W_fc = (const float*)d_in[5];
    const float* b_fc = (const float*)d_in[6];
    float* out = (float*)d_out;

    // 4096 chains, 2 per thread, 4 lanes per chain: 8192 threads.
    // 64 blocks x 128 threads -> 4 warps/SM on 64 SMs = 1 warp per SMSP;
    // latency hiding comes from the 2 independent chains inside each thread.
    gru_fused_kernel<<<(B / 2 * 4) / BLK, BLK>>>(x, W_ih, W_hh, b_ih, b_hh, W_fc, b_fc, out);
}

// round 8
// speedup vs baseline: 1.8375x; 1.8375x over previous
#include <cuda_runtime.h>

namespace {

constexpr int T = 2048;
constexpr int B = 4096;
constexpr int BLK = 256;   // 8 warps/block -> 2 warps per SMSP on 64 SMs
constexpr int PF = 4;      // x prefetch depth

typedef unsigned long long u64;

__device__ __forceinline__ u64 pack2(float lo, float hi) {
    u64 r; asm("mov.b64 %0,{%1,%2};" : "=l"(r) : "f"(lo), "f"(hi)); return r;
}
__device__ __forceinline__ void unpack2(u64 v, float& lo, float& hi) {
    asm("mov.b64 {%0,%1},%2;" : "=f"(lo), "=f"(hi) : "l"(v));
}
__device__ __forceinline__ u64 ffma2(u64 a, u64 b, u64 c) {
    u64 d; asm("fma.rn.f32x2 %0,%1,%2,%3;" : "=l"(d) : "l"(a), "l"(b), "l"(c)); return d;
}
__device__ __forceinline__ u64 fmul2(u64 a, u64 b) {
    u64 d; asm("mul.rn.f32x2 %0,%1,%2;" : "=l"(d) : "l"(a), "l"(b)); return d;
}
__device__ __forceinline__ float tanha(float x) {
    float y; asm("tanh.approx.f32 %0,%1;" : "=f"(y) : "f"(x)); return y;
}
__device__ __forceinline__ float hadd(u64 v) {
    float lo, hi; unpack2(v, lo, hi); return lo + hi;
}

// R6 structure (best: 422us): 4 threads/chain, thread q owns h-units {q,q+4},
// weight slots rotated so slot 0 is the local pair (3 foreign pairs via shfl),
// MUFU.TANH activations with 1/2 folded into r/z weights.
// NEW this round:
//  * WARP PHASE STAGGER: the two warps sharing an SMSP (w, w+4) are offset by
//    a one-time ~100-cycle dependent chain so their MUFU/SHFL/chain stalls
//    interleave instead of coinciding (no loop barriers -> offset persists).
//  * post-tanh path shortened: only one FFMA after each tanh on the h chain.
//  * prefetch depth 4.
__global__ void __launch_bounds__(BLK, 1) gru_fused_kernel(
    const float* __restrict__ x,
    const float* __restrict__ W_ih,
    const float* __restrict__ W_hh,
    const float* __restrict__ b_ih,
    const float* __restrict__ b_hh,
    const float* __restrict__ W_fc,
    const float* __restrict__ b_fc,
    float* __restrict__ out)
{
    const int tid = blockIdx.x * BLK + threadIdx.x;
    const int b = tid >> 2;
    const int q = tid & 3;

    const float HS = 0.5f;   // tanh-sigmoid pre-scale

    // ---- register-resident, pre-scaled, slot-rotated weights ----
    u64 Wr[2][4], Wz[2][4], Wn[2][4];   // [row A/B][slot k], k -> j=(q+k)&3
    u64 Xr[2][2], Xz[2][2], Xn[2][2];
    u64 Br[2], Bz[2], Bnx[2], Bnh[2];
#pragma unroll
    for (int rr = 0; rr < 2; rr++) {
        const int gr = q + 4 * rr;
        const int gz = 8 + q + 4 * rr;
        const int gn = 16 + q + 4 * rr;
#pragma unroll
        for (int k = 0; k < 4; k++) {
            const int j = (q + k) & 3;
            Wr[rr][k] = pack2(HS * W_hh[gr * 8 + j], HS * W_hh[gr * 8 + j + 4]);
            Wz[rr][k] = pack2(HS * W_hh[gz * 8 + j], HS * W_hh[gz * 8 + j + 4]);
            Wn[rr][k] = pack2(W_hh[gn * 8 + j], W_hh[gn * 8 + j + 4]);
        }
        Xr[rr][0] = pack2(HS * W_ih[gr * 4 + 0], HS * W_ih[gr * 4 + 2]);
        Xr[rr][1] = pack2(HS * W_ih[gr * 4 + 1], HS * W_ih[gr * 4 + 3]);
        Xz[rr][0] = pack2(HS * W_ih[gz * 4 + 0], HS * W_ih[gz * 4 + 2]);
        Xz[rr][1] = pack2(HS * W_ih[gz * 4 + 1], HS * W_ih[gz * 4 + 3]);
        Xn[rr][0] = pack2(W_ih[gn * 4 + 0], W_ih[gn * 4 + 2]);
        Xn[rr][1] = pack2(W_ih[gn * 4 + 1], W_ih[gn * 4 + 3]);
        Br[rr]  = pack2(HS * (b_ih[gr] + b_hh[gr]), 0.0f);
        Bz[rr]  = pack2(HS * (b_ih[gz] + b_hh[gz]), 0.0f);
        Bnx[rr] = pack2(b_ih[gn], 0.0f);
        Bnh[rr] = pack2(b_hh[gn], 0.0f);
    }
    u64 Wf[4];
#pragma unroll
    for (int k = 0; k < 4; k++) {
        const int j = (q + k) & 3;
        Wf[k] = pack2(W_fc[q * 8 + j], W_fc[q * 8 + j + 4]);
    }
    const u64 bfp = pack2(b_fc[q], 0.0f);

    const int j1 = (q + 1) & 3, j2 = (q + 2) & 3, j3 = (q + 3) & 3;

    const float4* xp = reinterpret_cast<const float4*>(x) + (size_t)b * T;
    float* op = out + (size_t)b * T * 4 + q;

    // ---- warp phase stagger: SMSP = wid&3; siblings are wid and wid+4.
    // Odd sibling runs a ~100-cycle dependent FMUL chain whose result is
    // EXACTLY 0 (1e-60 underflows) and is folded into h init.
    float stag = 0.0f;
    if ((threadIdx.x >> 7) & 1) {            // wid >= 4
        float acc = 1.0f + 1e-7f * (float)(q + 1);   // opaque to compiler
#pragma unroll
        for (int i = 0; i < 25; i++) acc = acc * 0.99999988f;
        stag = acc * 1e-30f * 1e-30f;        // == 0.0f exactly
    }

    float hA = stag, hB = stag;
    u64 p0 = 0, p1 = 0, p2 = 0, p3 = 0;     // slot-k pairs; p0 local

    // PF-deep x prefetch pipeline
    float4 xb[PF];
#pragma unroll
    for (int i = 0; i < PF; i++) xb[i] = xp[i];

#pragma unroll 2
    for (int t = 0; t < T; t++) {
        float4 xc = xb[0];
#pragma unroll
        for (int i = 0; i < PF - 1; i++) xb[i] = xb[i + 1];
        int tn = t + PF; tn = (tn < T) ? tn : (T - 1);
        xb[PF - 1] = xp[tn];

        // ---- emit y_{t-1} from p (overlaps the in-flight shfl latency) ----
        {
            u64 ya = ffma2(Wf[0], p0, ffma2(Wf[1], p1, bfp));
            u64 yb = ffma2(Wf[2], p2, fmul2(Wf[3], p3));
            float yl, yh, yl2, yh2;
            unpack2(ya, yl, yh); unpack2(yb, yl2, yh2);
            int tp = t - (t > 0);
            op[tp * 4] = (yl + yh) + (yl2 + yh2);
        }

        // ---- x-side accumulators (off the h-chain) ----
        const u64 xq0 = pack2(xc.x, xc.z);
        const u64 xq1 = pack2(xc.y, xc.w);
        u64 aR[2], aZ[2], aNX[2], aNH[2];
#pragma unroll
        for (int rr = 0; rr < 2; rr++) {
            aR[rr]  = ffma2(Xr[rr][1], xq1, ffma2(Xr[rr][0], xq0, Br[rr]));
            aZ[rr]  = ffma2(Xz[rr][1], xq1, ffma2(Xz[rr][0], xq0, Bz[rr]));
            aNX[rr] = ffma2(Xn[rr][1], xq1, ffma2(Xn[rr][0], xq0, Bnx[rr]));
            aNH[rr] = Bnh[rr];
        }

        // ---- h-side: depth-4 FFMA2 chains fed by shfl pairs ----
#pragma unroll
        for (int rr = 0; rr < 2; rr++) {
            aR[rr]  = ffma2(Wr[rr][0], p0, aR[rr]);
            aR[rr]  = ffma2(Wr[rr][1], p1, aR[rr]);
            aR[rr]  = ffma2(Wr[rr][2], p2, aR[rr]);
            aR[rr]  = ffma2(Wr[rr][3], p3, aR[rr]);
            aZ[rr]  = ffma2(Wz[rr][0], p0, aZ[rr]);
            aZ[rr]  = ffma2(Wz[rr][1], p1, aZ[rr]);
            aZ[rr]  = ffma2(Wz[rr][2], p2, aZ[rr]);
            aZ[rr]  = ffma2(Wz[rr][3], p3, aZ[rr]);
            aNH[rr] = ffma2(Wn[rr][0], p0, aNH[rr]);
            aNH[rr] = ffma2(Wn[rr][1], p1, aNH[rr]);
            aNH[rr] = ffma2(Wn[rr][2], p2, aNH[rr]);
            aNH[rr] = ffma2(Wn[rr][3], p3, aNH[rr]);
        }

        // ---- activations; only ONE FFMA follows each tanh on the chain ----
        const float thrA = tanha(hadd(aR[0]));   // tanh(u_r/2)
        const float thrB = tanha(hadd(aR[1]));
        const float thzA = tanha(hadd(aZ[0]));   // tanh(u_z/2)
        const float thzB = tanha(hadd(aZ[1]));

        const float hnA = hadd(aNH[0]), hnB = hadd(aNH[1]);
        const float xnA = hadd(aNX[0]), xnB = hadd(aNX[1]);
        // v = r*hn + xn = thr*(hn/2) + (hn/2 + xn)
        const float hn2A = 0.5f * hnA, hn2B = 0.5f * hnB;
        const float vA = fmaf(thrA, hn2A, hn2A + xnA);
        const float vB = fmaf(thrB, hn2B, hn2B + xnB);
        const float nA = tanha(vA);
        const float nB = tanha(vB);

        // h = (1-z)*n + z*h ; z = 0.5 + 0.5*thz
        // omz = 0.5 - 0.5*thz  (off n-chain), zh = 0.5*h + 0.5*thz*h (off n-chain)
        const float omzA = fmaf(-0.5f, thzA, 0.5f);
        const float omzB = fmaf(-0.5f, thzB, 0.5f);
        const float hh2A = 0.5f * hA, hh2B = 0.5f * hB;
        const float zhA = fmaf(thzA, hh2A, hh2A);
        const float zhB = fmaf(thzB, hh2B, hh2B);
        hA = fmaf(omzA, nA, zhA);    // single FFMA after nA
        hB = fmaf(omzB, nB, zhB);

        // ---- exchange: local pair + 3 foreign pairs via 64-bit shfl ----
        p0 = pack2(hA, hB);
        double hd = __longlong_as_double((long long)p0);
        p1 = (u64)__double_as_longlong(__shfl_sync(0xffffffffu, hd, j1, 4));
        p2 = (u64)__double_as_longlong(__shfl_sync(0xffffffffu, hd, j2, 4));
        p3 = (u64)__double_as_longlong(__shfl_sync(0xffffffffu, hd, j3, 4));
    }

    // ---- final y_{T-1} ----
    {
        u64 ya = ffma2(Wf[0], p0, ffma2(Wf[1], p1, bfp));
        u64 yb = ffma2(Wf[2], p2, fmul2(Wf[3], p3));
        float yl, yh, yl2, yh2;
        unpack2(ya, yl, yh); unpack2(yb, yl2, yh2);
        op[(T - 1) * 4] = (yl + yh) + (yl2 + yh2);
    }
}

} // namespace

extern "C" void kernel_launch(void* const* d_in, const int* in_sizes, int n_in,
                              void* d_out, int out_size)
{
    const float* x    = (const float*)d_in[0];
    const float* W_ih = (const float*)d_in[1];
    const float* W_hh = (const float*)d_in[2];
    const float* b_ih = (const float*)d_in[3];
    const float* b_hh = (const float*)d_in[4];
    const float* W_fc = (const float*)d_in[5];
    const float* b_fc = (const float*)d_in[6];
    float* out = (float*)d_out;

    // 16384 threads as 64 blocks x 256: 2 warps/SMSP on 64 SMs, with the
    // sibling warps phase-staggered so their stalls interleave.
    gru_fused_kernel<<<(B * 4) / BLK, BLK>>>(x, W_ih, W_hh, b_ih, b_hh, W_fc, b_fc, out);
}

// round 10
// speedup vs baseline: 2.4084x; 1.3107x over previous
#include <cuda_runtime.h>

namespace {

constexpr int T = 2048;
constexpr int B = 4096;
constexpr int BLK = 256;   // 32 chains/block; 128 blocks; 2 warps/SMSP on 128 SMs
constexpr int PF = 3;      // x prefetch depth

typedef unsigned long long u64;

__device__ __forceinline__ u64 pack2(float lo, float hi) {
    u64 r; asm("mov.b64 %0,{%1,%2};" : "=l"(r) : "f"(lo), "f"(hi)); return r;
}
__device__ __forceinline__ void unpack2(u64 v, float& lo, float& hi) {
    asm("mov.b64 {%0,%1},%2;" : "=f"(lo), "=f"(hi) : "l"(v));
}
__device__ __forceinline__ u64 ffma2(u64 a, u64 b, u64 c) {
    u64 d; asm("fma.rn.f32x2 %0,%1,%2,%3;" : "=l"(d) : "l"(a), "l"(b), "l"(c)); return d;
}
__device__ __forceinline__ u64 fmul2(u64 a, u64 b) {
    u64 d; asm("mul.rn.f32x2 %0,%1,%2;" : "=l"(d) : "l"(a), "l"(b)); return d;
}
__device__ __forceinline__ float tanha(float x) {
    float y; asm("tanh.approx.f32 %0,%1;" : "=f"(y) : "f"(x)); return y;
}
__device__ __forceinline__ float hadd(u64 v) {
    float lo, hi; unpack2(v, lo, hi); return lo + hi;
}
__device__ __forceinline__ unsigned smem_u32(const void* p) {
    unsigned a;
    asm("{ .reg .u64 t; cvta.to.shared.u64 t, %1; cvt.u32.u64 %0, t; }" : "=r"(a) : "l"(p));
    return a;
}

// 8 threads per batch chain. Lane l (0..7 within the group) owns hidden unit
// h_l and computes exactly rows l (r), 8+l (z), 16+l (n) — per-thread math is
// HALF of the 4-thread layout and tanh count drops 6 -> 3 per thread.
// h exchange via warp-synchronous shared memory: STS.32 of h_l, then two
// LDS.128 deliver the full 8-float h as ready-made f32x2 operand pairs
// (h0,h1)(h2,h3)(h4,h5)(h6,h7) — no shfl, no packing. x is loaded as
// ulonglong2 so (x0,x1)(x2,x3) pairs are also free.
// Gate algebra: r/z rows pre-scaled by 1/2 -> sigma(u) = 0.5 + 0.5*tanh(acc);
// n = tanh(xn + 0.5*hn + thr*0.5*hn).
__global__ void __launch_bounds__(BLK, 1) gru_fused_kernel(
    const float* __restrict__ x,
    const float* __restrict__ W_ih,
    const float* __restrict__ W_hh,
    const float* __restrict__ b_ih,
    const float* __restrict__ b_hh,
    const float* __restrict__ W_fc,
    const float* __restrict__ b_fc,
    float* __restrict__ out)
{
    __shared__ float hx[BLK];              // 32 groups x 8 floats = 1KB

    const int l  = threadIdx.x & 7;        // lane within chain group
    const int gi = threadIdx.x >> 3;       // group within block
    const int b  = blockIdx.x * (BLK / 8) + gi;

    const unsigned sbase = smem_u32(hx) + gi * 32;   // this group's 8-float slab
    const unsigned sme   = sbase + l * 4;            // my h slot

    const float HS = 0.5f;

    // ---- register-resident weights: rows l, 8+l, 16+l; pairs over input idx ----
    const int gr = l, gz = 8 + l, gn = 16 + l;
    u64 Whr[4], Whz[4], Whn[4];            // (W[g,2k], W[g,2k+1])
#pragma unroll
    for (int k = 0; k < 4; k++) {
        Whr[k] = pack2(HS * W_hh[gr * 8 + 2 * k], HS * W_hh[gr * 8 + 2 * k + 1]);
        Whz[k] = pack2(HS * W_hh[gz * 8 + 2 * k], HS * W_hh[gz * 8 + 2 * k + 1]);
        Whn[k] = pack2(W_hh[gn * 8 + 2 * k], W_hh[gn * 8 + 2 * k + 1]);
    }
    u64 Wxr[2], Wxz[2], Wxn[2];            // (W[g,0],W[g,1]), (W[g,2],W[g,3])
#pragma unroll
    for (int k = 0; k < 2; k++) {
        Wxr[k] = pack2(HS * W_ih[gr * 4 + 2 * k], HS * W_ih[gr * 4 + 2 * k + 1]);
        Wxz[k] = pack2(HS * W_ih[gz * 4 + 2 * k], HS * W_ih[gz * 4 + 2 * k + 1]);
        Wxn[k] = pack2(W_ih[gn * 4 + 2 * k], W_ih[gn * 4 + 2 * k + 1]);
    }
    const u64 brp  = pack2(HS * (b_ih[gr] + b_hh[gr]), 0.0f);
    const u64 bzp  = pack2(HS * (b_ih[gz] + b_hh[gz]), 0.0f);
    const u64 bxnp = pack2(b_ih[gn], 0.0f);
    const u64 bhnp = pack2(b_hh[gn], 0.0f);

    const int o = l & 3;                   // fc output index (lanes 4-7 redundant)
    u64 Wf[4];
#pragma unroll
    for (int k = 0; k < 4; k++)
        Wf[k] = pack2(W_fc[o * 8 + 2 * k], W_fc[o * 8 + 2 * k + 1]);
    const u64 bfp = pack2(b_fc[o], 0.0f);

    const ulonglong2* xp = reinterpret_cast<const ulonglong2*>(x) + (size_t)b * T;
    float* op = out + (size_t)b * T * 4 + o;

    // h_{t-1} pairs; h0 = 0
    u64 H01 = 0, H23 = 0, H45 = 0, H67 = 0;
    float h = 0.0f;                        // my owned h_l

    // PF-deep x prefetch pipeline (ulonglong2 -> free (x0,x1)(x2,x3) pairs)
    ulonglong2 xb[PF];
#pragma unroll
    for (int i = 0; i < PF; i++) xb[i] = xp[i];

#pragma unroll 2
    for (int t = 0; t < T; t++) {
        const u64 xp0 = xb[0].x, xp1 = xb[0].y;
#pragma unroll
        for (int i = 0; i < PF - 1; i++) xb[i] = xb[i + 1];
        int tn = t + PF; tn = (tn < T) ? tn : (T - 1);
        xb[PF - 1] = xp[tn];

        // ---- row accumulators: x part (off-chain) then h part ----
        u64 aR = ffma2(Wxr[1], xp1, ffma2(Wxr[0], xp0, brp));
        u64 aZ = ffma2(Wxz[1], xp1, ffma2(Wxz[0], xp0, bzp));
        u64 aX = ffma2(Wxn[1], xp1, ffma2(Wxn[0], xp0, bxnp));
        u64 aN = bhnp;

        aR = ffma2(Whr[0], H01, aR);
        aR = ffma2(Whr[1], H23, aR);
        aR = ffma2(Whr[2], H45, aR);
        aR = ffma2(Whr[3], H67, aR);
        aZ = ffma2(Whz[0], H01, aZ);
        aZ = ffma2(Whz[1], H23, aZ);
        aZ = ffma2(Whz[2], H45, aZ);
        aZ = ffma2(Whz[3], H67, aZ);
        aN = ffma2(Whn[0], H01, aN);
        aN = ffma2(Whn[1], H23, aN);
        aN = ffma2(Whn[2], H45, aN);
        aN = ffma2(Whn[3], H67, aN);

        // ---- activations (one tanh per gate; sigmoid scales pre-folded) ----
        const float thr = tanha(hadd(aR));         // tanh(u_r/2)
        const float thz = tanha(hadd(aZ));         // tanh(u_z/2)
        const float hn  = hadd(aN);
        const float xn  = hadd(aX);
        const float hn2 = 0.5f * hn;
        const float v   = fmaf(thr, hn2, hn2 + xn);
        const float n   = tanha(v);

        // h' = (1-z)n + z h ;  z = 0.5 + 0.5*thz
        const float omz = fmaf(-0.5f, thz, 0.5f);
        const float hh2 = 0.5f * h;
        const float zh  = fmaf(thz, hh2, hh2);
        h = fmaf(omz, n, zh);

        // ---- exchange: warp-synchronous smem (same warp, uniform flow) ----
        asm volatile("st.volatile.shared.f32 [%0], %1;" :: "r"(sme), "f"(h) : "memory");
        asm volatile("ld.volatile.shared.v2.b64 {%0,%1}, [%2];"
                     : "=l"(H01), "=l"(H23) : "r"(sbase) : "memory");
        asm volatile("ld.volatile.shared.v2.b64 {%0,%1}, [%2];"
                     : "=l"(H45), "=l"(H67) : "r"(sbase + 16) : "memory");

        // ---- y_t from fresh pairs; lanes 0-3 store ----
        u64 ya = ffma2(Wf[0], H01, ffma2(Wf[1], H23, bfp));
        u64 yb = ffma2(Wf[2], H45, fmul2(Wf[3], H67));
        const float y = hadd(ya) + hadd(yb);
        if (l < 4) op[t * 4] = y;
    }
}

} // namespace

extern "C" void kernel_launch(void* const* d_in, const int* in_sizes, int n_in,
                              void* d_out, int out_size)
{
    const float* x    = (const float*)d_in[0];
    const float* W_ih = (const float*)d_in[1];
    const float* W_hh = (const float*)d_in[2];
    const float* b_ih = (const float*)d_in[3];
    const float* b_hh = (const float*)d_in[4];
    const float* W_fc = (const float*)d_in[5];
    const float* b_fc = (const float*)d_in[6];
    float* out = (float*)d_out;

    // 4096 chains x 8 lanes = 32768 threads; 128 blocks x 256 threads
    // -> 8 warps/SM on 128 SMs = 2 warps/SMSP.
    gru_fused_kernel<<<(B * 8) / BLK, BLK>>>(x, W_ih, W_hh, b_ih, b_hh, W_fc, b_fc, out);
}

// round 11
// speedup vs baseline: 2.6813x; 1.1133x over previous
#include <cuda_runtime.h>

namespace {

constexpr int T = 2048;
constexpr int B = 4096;
constexpr int BLK = 256;   // 32 chains/block; 128 blocks; 2 warps/SMSP on 128 SMs
constexpr int PF = 4;      // x prefetch depth (matched to unroll for free shifts)

typedef unsigned long long u64;

__device__ __forceinline__ u64 pack2(float lo, float hi) {
    u64 r; asm("mov.b64 %0,{%1,%2};" : "=l"(r) : "f"(lo), "f"(hi)); return r;
}
__device__ __forceinline__ void unpack2(u64 v, float& lo, float& hi) {
    asm("mov.b64 {%0,%1},%2;" : "=f"(lo), "=f"(hi) : "l"(v));
}
__device__ __forceinline__ u64 ffma2(u64 a, u64 b, u64 c) {
    u64 d; asm("fma.rn.f32x2 %0,%1,%2,%3;" : "=l"(d) : "l"(a), "l"(b), "l"(c)); return d;
}
__device__ __forceinline__ u64 fmul2(u64 a, u64 b) {
    u64 d; asm("mul.rn.f32x2 %0,%1,%2;" : "=l"(d) : "l"(a), "l"(b)); return d;
}
__device__ __forceinline__ u64 fadd2(u64 a, u64 b) {
    u64 d; asm("add.rn.f32x2 %0,%1,%2;" : "=l"(d) : "l"(a), "l"(b)); return d;
}
__device__ __forceinline__ float tanha(float x) {
    float y; asm("tanh.approx.f32 %0,%1;" : "=f"(y) : "f"(x)); return y;
}
__device__ __forceinline__ float hadd(u64 v) {
    float lo, hi; unpack2(v, lo, hi); return lo + hi;
}
__device__ __forceinline__ unsigned smem_u32(const void* p) {
    unsigned a;
    asm("{ .reg .u64 t; cvta.to.shared.u64 t, %1; cvt.u32.u64 %0, t; }" : "=r"(a) : "l"(p));
    return a;
}

// 8 threads per batch chain; lane l owns h_l and rows l (r), 8+l (z), 16+l (n).
// Exchange: plain STS.32 + __syncwarp + two PIPELINED LDS.128 that deliver h as
// ready-made f32x2 pairs (volatile serialization removed vs R10: the two loads
// no longer wait on each other or on store commit beyond the 23-cyc barrier).
// Gate rows in tree form: two depth-2 FFMA2 half-chains seeded by the x-part,
// joined by fadd2 — post-exchange depth ~16 cyc instead of 24.
// Activations: MUFU.TANH; sigma(u) = 0.5 + 0.5*tanh(u/2) with 1/2 pre-folded.
__global__ void __launch_bounds__(BLK, 1) gru_fused_kernel(
    const float* __restrict__ x,
    const float* __restrict__ W_ih,
    const float* __restrict__ W_hh,
    const float* __restrict__ b_ih,
    const float* __restrict__ b_hh,
    const float* __restrict__ W_fc,
    const float* __restrict__ b_fc,
    float* __restrict__ out)
{
    __shared__ float hx[BLK];              // 32 groups x 8 floats = 1KB

    const int l  = threadIdx.x & 7;        // lane within chain group
    const int gi = threadIdx.x >> 3;       // group within block
    const int b  = blockIdx.x * (BLK / 8) + gi;

    const unsigned sbase = smem_u32(hx) + gi * 32;   // group's 8-float slab
    const unsigned sme   = sbase + l * 4;            // my h slot

    const float HS = 0.5f;

    // ---- register-resident weights: rows l, 8+l, 16+l ----
    const int gr = l, gz = 8 + l, gn = 16 + l;
    u64 Whr[4], Whz[4], Whn[4];            // (W[g,2k], W[g,2k+1])
#pragma unroll
    for (int k = 0; k < 4; k++) {
        Whr[k] = pack2(HS * W_hh[gr * 8 + 2 * k], HS * W_hh[gr * 8 + 2 * k + 1]);
        Whz[k] = pack2(HS * W_hh[gz * 8 + 2 * k], HS * W_hh[gz * 8 + 2 * k + 1]);
        Whn[k] = pack2(W_hh[gn * 8 + 2 * k], W_hh[gn * 8 + 2 * k + 1]);
    }
    u64 Wxr[2], Wxz[2], Wxn[2];
#pragma unroll
    for (int k = 0; k < 2; k++) {
        Wxr[k] = pack2(HS * W_ih[gr * 4 + 2 * k], HS * W_ih[gr * 4 + 2 * k + 1]);
        Wxz[k] = pack2(HS * W_ih[gz * 4 + 2 * k], HS * W_ih[gz * 4 + 2 * k + 1]);
        Wxn[k] = pack2(W_ih[gn * 4 + 2 * k], W_ih[gn * 4 + 2 * k + 1]);
    }
    const u64 brp  = pack2(HS * (b_ih[gr] + b_hh[gr]), 0.0f);
    const u64 bzp  = pack2(HS * (b_ih[gz] + b_hh[gz]), 0.0f);
    const u64 bxnp = pack2(b_ih[gn], 0.0f);
    const u64 bhnp = pack2(b_hh[gn], 0.0f);

    const int o = l & 3;                   // fc output index (lanes 4-7 redundant)
    u64 Wf[4];
#pragma unroll
    for (int k = 0; k < 4; k++)
        Wf[k] = pack2(W_fc[o * 8 + 2 * k], W_fc[o * 8 + 2 * k + 1]);
    const u64 bfp = pack2(b_fc[o], 0.0f);

    const ulonglong2* xp = reinterpret_cast<const ulonglong2*>(x) + (size_t)b * T;
    float* op = out + (size_t)b * T * 4 + o;

    u64 H01 = 0, H23 = 0, H45 = 0, H67 = 0;   // h_{t-1} pairs
    float h = 0.0f;                            // my owned h_l

    // PF-deep x prefetch; loop unrolled by PF so shifts are register renaming
    ulonglong2 xb[PF];
#pragma unroll
    for (int i = 0; i < PF; i++) xb[i] = xp[i];

#pragma unroll 4
    for (int t = 0; t < T; t++) {
        const u64 xp0 = xb[0].x, xp1 = xb[0].y;
#pragma unroll
        for (int i = 0; i < PF - 1; i++) xb[i] = xb[i + 1];
        int tn = t + PF; tn = (tn < T) ? tn : (T - 1);
        xb[PF - 1] = xp[tn];

        // ---- gate rows, tree form: two half-chains seeded by the x-part ----
        u64 r1 = ffma2(Wxr[0], xp0, brp);
        u64 r2 = fmul2(Wxr[1], xp1);
        r1 = ffma2(Whr[0], H01, r1);
        r2 = ffma2(Whr[2], H45, r2);
        r1 = ffma2(Whr[1], H23, r1);
        r2 = ffma2(Whr[3], H67, r2);

        u64 z1 = ffma2(Wxz[0], xp0, bzp);
        u64 z2 = fmul2(Wxz[1], xp1);
        z1 = ffma2(Whz[0], H01, z1);
        z2 = ffma2(Whz[2], H45, z2);
        z1 = ffma2(Whz[1], H23, z1);
        z2 = ffma2(Whz[3], H67, z2);

        u64 n1 = ffma2(Wxn[0], xp0, bhnp);
        u64 n2 = fmul2(Wxn[1], xp1);
        n1 = ffma2(Whn[0], H01, n1);
        n2 = ffma2(Whn[2], H45, n2);
        n1 = ffma2(Whn[1], H23, n1);
        n2 = ffma2(Whn[3], H67, n2);
        // NOTE: n1 seeded with b_hh only; xn part = Wxn*x + b_ih tracked via bxnp:
        u64 ax = bxnp;                       // xn bias (kept separate for hn split)

        // hn = (Whn·h + b_hh);  xn = (Wxn·x + b_ih)
        // We fused Wxn·x into the hn tree above, so reconstruct:
        //   aNall = hn + xn  (without r weighting we need hn separately!)
        // -> keep them separate instead: undo fusion by computing xn tree alone.
        // (Wxn·x was added into n1/n2; subtract is wrong numerically — instead
        //  n1/n2 above ARE hn+xn-without-b_ih; handle algebra below.)
        // v = xn + r*hn = (hn+xn) + (r-1)*hn ... needs hn alone; so recompute:
        // To keep it simple and correct: aH = Whn·h + b_hh ; aXn = Wxn·x + b_ih.
        (void)ax;

        const float thr = tanha(hadd(fadd2(r1, r2)));   // tanh(u_r/2)
        const float thz = tanha(hadd(fadd2(z1, z2)));   // tanh(u_z/2)

        // hn-only tree (Whn·h + b_hh):
        u64 hn1 = ffma2(Whn[1], H23, ffma2(Whn[0], H01, bhnp));
        u64 hn2p = ffma2(Whn[3], H67, fmul2(Whn[2], H45));
        const float hn = hadd(fadd2(hn1, hn2p));
        // xn-only (Wxn·x + b_ih):
        const float xn = hadd(ffma2(Wxn[1], xp1, ffma2(Wxn[0], xp0, bxnp)));

        const float hnh = 0.5f * hn;
        const float vpre = hnh + xn;                    // off-chain of thr
        const float v = fmaf(thr, hnh, vpre);
        const float n = tanha(v);

        const float omz = fmaf(-0.5f, thz, 0.5f);
        const float hh2 = 0.5f * h;
        const float zh  = fmaf(thz, hh2, hh2);
        h = fmaf(omz, n, zh);

        // ---- exchange: STS + syncwarp + pipelined LDS.128 pair loads ----
        asm volatile("st.shared.f32 [%0], %1;" :: "r"(sme), "f"(h) : "memory");
        __syncwarp(0xffffffffu);
        asm volatile("ld.shared.v2.b64 {%0,%1}, [%2];"
                     : "=l"(H01), "=l"(H23) : "r"(sbase) : "memory");
        asm volatile("ld.shared.v2.b64 {%0,%1}, [%2];"
                     : "=l"(H45), "=l"(H67) : "r"(sbase + 16) : "memory");

        // ---- y_t from fresh pairs; lanes 0-3 store ----
        u64 ya = ffma2(Wf[0], H01, ffma2(Wf[1], H23, bfp));
        u64 yb = ffma2(Wf[2], H45, fmul2(Wf[3], H67));
        const float y = hadd(ya) + hadd(yb);
        if (l < 4) op[t * 4] = y;
    }
}

} // namespace

extern "C" void kernel_launch(void* const* d_in, const int* in_sizes, int n_in,
                              void* d_out, int out_size)
{
    const float* x    = (const float*)d_in[0];
    const float* W_ih = (const float*)d_in[1];
    const float* W_hh = (const float*)d_in[2];
    const float* b_ih = (const float*)d_in[3];
    const float* b_hh = (const float*)d_in[4];
    const float* W_fc = (const float*)d_in[5];
    const float* b_fc = (const float*)d_in[6];
    float* out = (float*)d_out;

    // 4096 chains x 8 lanes = 32768 threads; 128 blocks x 256 threads
    // -> 8 warps/SM on 128 SMs = 2 warps/SMSP.
    gru_fused_kernel<<<(B * 8) / BLK, BLK>>>(x, W_ih, W_hh, b_ih, b_hh, W_fc, b_fc, out);
}

// round 12
// speedup vs baseline: 2.8286x; 1.0549x over previous
#include <cuda_runtime.h>

namespace {

constexpr int T = 2048;
constexpr int B = 4096;
constexpr int BLK = 256;   // 32 chains/block; 128 blocks; 2 warps/SMSP on 128 SMs
constexpr int PF = 4;      // x prefetch depth (matched to unroll for free shifts)

typedef unsigned long long u64;

__device__ __forceinline__ u64 pack2(float lo, float hi) {
    u64 r; asm("mov.b64 %0,{%1,%2};" : "=l"(r) : "f"(lo), "f"(hi)); return r;
}
__device__ __forceinline__ void unpack2(u64 v, float& lo, float& hi) {
    asm("mov.b64 {%0,%1},%2;" : "=f"(lo), "=f"(hi) : "l"(v));
}
__device__ __forceinline__ u64 ffma2(u64 a, u64 b, u64 c) {
    u64 d; asm("fma.rn.f32x2 %0,%1,%2,%3;" : "=l"(d) : "l"(a), "l"(b), "l"(c)); return d;
}
__device__ __forceinline__ u64 fmul2(u64 a, u64 b) {
    u64 d; asm("mul.rn.f32x2 %0,%1,%2;" : "=l"(d) : "l"(a), "l"(b)); return d;
}
__device__ __forceinline__ u64 fadd2(u64 a, u64 b) {
    u64 d; asm("add.rn.f32x2 %0,%1,%2;" : "=l"(d) : "l"(a), "l"(b)); return d;
}
__device__ __forceinline__ float tanha(float x) {
    float y; asm("tanh.approx.f32 %0,%1;" : "=f"(y) : "f"(x)); return y;
}
__device__ __forceinline__ float hadd(u64 v) {
    float lo, hi; unpack2(v, lo, hi); return lo + hi;
}
__device__ __forceinline__ unsigned smem_u32(const void* p) {
    unsigned a;
    asm("{ .reg .u64 t; cvta.to.shared.u64 t, %1; cvt.u32.u64 %0, t; }" : "=r"(a) : "l"(p));
    return a;
}

// 8 threads per batch chain; lane l owns h_l and rows l (r), 8+l (z), 16+l (n).
// Exchange: plain STS.32 then two LDS.128 with NO warp barrier — the LSU
// processes same-warp shared-memory ops in program order (proven correct in
// R10's volatile variant), and compiler motion is pinned by asm volatile +
// memory clobbers + unprovable aliasing. LDS.128 delivers h as ready-made
// f32x2 pairs (h0,h1)(h2,h3)(h4,h5)(h6,h7).
// Gate rows in tree form (two depth-2 FFMA2 half-chains joined by fadd2).
// n-path: 0.5 pre-folded into Whn/bhn so the tree yields hnh = hn/2 directly;
// v = xn + (0.5+0.5*thr)*hn = fma(thr, hnh, hnh + xn). sigma via MUFU.TANH
// with 1/2 pre-folded into r/z weights.
__global__ void __launch_bounds__(BLK, 1) gru_fused_kernel(
    const float* __restrict__ x,
    const float* __restrict__ W_ih,
    const float* __restrict__ W_hh,
    const float* __restrict__ b_ih,
    const float* __restrict__ b_hh,
    const float* __restrict__ W_fc,
    const float* __restrict__ b_fc,
    float* __restrict__ out)
{
    __shared__ float hx[BLK];              // 32 groups x 8 floats = 1KB

    const int l  = threadIdx.x & 7;        // lane within chain group
    const int gi = threadIdx.x >> 3;       // group within block
    const int b  = blockIdx.x * (BLK / 8) + gi;

    const unsigned sbase = smem_u32(hx) + gi * 32;   // group's 8-float slab
    const unsigned sme   = sbase + l * 4;            // my h slot

    const float HS = 0.5f;

    // ---- register-resident weights: rows l, 8+l, 16+l ----
    const int gr = l, gz = 8 + l, gn = 16 + l;
    u64 Whr[4], Whz[4], Whn[4];            // (W[g,2k], W[g,2k+1])
#pragma unroll
    for (int k = 0; k < 4; k++) {
        Whr[k] = pack2(HS * W_hh[gr * 8 + 2 * k], HS * W_hh[gr * 8 + 2 * k + 1]);
        Whz[k] = pack2(HS * W_hh[gz * 8 + 2 * k], HS * W_hh[gz * 8 + 2 * k + 1]);
        // 0.5 folded here too: tree yields hnh = 0.5*(Whn·h + b_hh)
        Whn[k] = pack2(HS * W_hh[gn * 8 + 2 * k], HS * W_hh[gn * 8 + 2 * k + 1]);
    }
    u64 Wxr[2], Wxz[2], Wxn[2];
#pragma unroll
    for (int k = 0; k < 2; k++) {
        Wxr[k] = pack2(HS * W_ih[gr * 4 + 2 * k], HS * W_ih[gr * 4 + 2 * k + 1]);
        Wxz[k] = pack2(HS * W_ih[gz * 4 + 2 * k], HS * W_ih[gz * 4 + 2 * k + 1]);
        Wxn[k] = pack2(W_ih[gn * 4 + 2 * k], W_ih[gn * 4 + 2 * k + 1]);
    }
    const u64 brp   = pack2(HS * (b_ih[gr] + b_hh[gr]), 0.0f);
    const u64 bzp   = pack2(HS * (b_ih[gz] + b_hh[gz]), 0.0f);
    const u64 bxnp  = pack2(b_ih[gn], 0.0f);
    const u64 bhn2p = pack2(HS * b_hh[gn], 0.0f);     // pre-halved n-bias

    const int o = l & 3;                   // fc output index (lanes 4-7 redundant)
    u64 Wf[4];
#pragma unroll
    for (int k = 0; k < 4; k++)
        Wf[k] = pack2(W_fc[o * 8 + 2 * k], W_fc[o * 8 + 2 * k + 1]);
    const u64 bfp = pack2(b_fc[o], 0.0f);

    const ulonglong2* xp = reinterpret_cast<const ulonglong2*>(x) + (size_t)b * T;
    float* op = out + (size_t)b * T * 4 + o;

    u64 H01 = 0, H23 = 0, H45 = 0, H67 = 0;   // h_{t-1} pairs
    float h = 0.0f;                            // my owned h_l

    // PF-deep x prefetch; loop unrolled by PF so shifts are register renaming
    ulonglong2 xb[PF];
#pragma unroll
    for (int i = 0; i < PF; i++) xb[i] = xp[i];

#pragma unroll 4
    for (int t = 0; t < T; t++) {
        const u64 xp0 = xb[0].x, xp1 = xb[0].y;
#pragma unroll
        for (int i = 0; i < PF - 1; i++) xb[i] = xb[i + 1];
        int tn = t + PF; tn = (tn < T) ? tn : (T - 1);
        xb[PF - 1] = xp[tn];

        // ---- gate rows, tree form: two half-chains seeded by the x-part ----
        u64 r1 = ffma2(Wxr[0], xp0, brp);
        u64 r2 = fmul2(Wxr[1], xp1);
        r1 = ffma2(Whr[0], H01, r1);
        r2 = ffma2(Whr[2], H45, r2);
        r1 = ffma2(Whr[1], H23, r1);
        r2 = ffma2(Whr[3], H67, r2);

        u64 z1 = ffma2(Wxz[0], xp0, bzp);
        u64 z2 = fmul2(Wxz[1], xp1);
        z1 = ffma2(Whz[0], H01, z1);
        z2 = ffma2(Whz[2], H45, z2);
        z1 = ffma2(Whz[1], H23, z1);
        z2 = ffma2(Whz[3], H67, z2);

        // hnh tree: 0.5*(Whn·h + b_hh) — scale pre-folded into Whn/bhn2p
        u64 hn1 = ffma2(Whn[1], H23, ffma2(Whn[0], H01, bhn2p));
        u64 hn2 = ffma2(Whn[3], H67, fmul2(Whn[2], H45));
        // xn tree (x only, off the h-chain): Wxn·x + b_ih
        u64 xnp = ffma2(Wxn[1], xp1, ffma2(Wxn[0], xp0, bxnp));

        const float thr = tanha(hadd(fadd2(r1, r2)));   // tanh(u_r/2)
        const float thz = tanha(hadd(fadd2(z1, z2)));   // tanh(u_z/2)

        const float hnh = hadd(fadd2(hn1, hn2));        // hn/2
        const float xn  = hadd(xnp);
        const float v   = fmaf(thr, hnh, hnh + xn);     // xn + r*hn
        const float n   = tanha(v);

        // h' = (1-z)n + z h ;  z = 0.5 + 0.5*thz
        const float omz = fmaf(-0.5f, thz, 0.5f);
        const float hh2 = 0.5f * h;                      // off-chain (old h)
        const float zh  = fmaf(thz, hh2, hh2);
        h = fmaf(omz, n, zh);

        // ---- exchange: STS then pipelined LDS.128 (same-warp LSU ordering;
        //      asm volatile + clobbers pin the compiler) ----
        asm volatile("st.shared.f32 [%0], %1;" :: "r"(sme), "f"(h) : "memory");
        asm volatile("ld.shared.v2.b64 {%0,%1}, [%2];"
                     : "=l"(H01), "=l"(H23) : "r"(sbase) : "memory");
        asm volatile("ld.shared.v2.b64 {%0,%1}, [%2];"
                     : "=l"(H45), "=l"(H67) : "r"(sbase + 16) : "memory");

        // ---- y_t from fresh pairs; lanes 0-3 store ----
        u64 ya = ffma2(Wf[0], H01, ffma2(Wf[1], H23, bfp));
        u64 yb = ffma2(Wf[2], H45, fmul2(Wf[3], H67));
        const float y = hadd(ya) + hadd(yb);
        if (l < 4) op[t * 4] = y;
    }
}

} // namespace

extern "C" void kernel_launch(void* const* d_in, const int* in_sizes, int n_in,
                              void* d_out, int out_size)
{
    const float* x    = (const float*)d_in[0];
    const float* W_ih = (const float*)d_in[1];
    const float* W_hh = (const float*)d_in[2];
    const float* b_ih = (const float*)d_in[3];
    const float* b_hh = (const float*)d_in[4];
    const float* W_fc = (const float*)d_in[5];
    const float* b_fc = (const float*)d_in[6];
    float* out = (float*)d_out;

    // 4096 chains x 8 lanes = 32768 threads; 128 blocks x 256 threads
    // -> 8 warps/SM on 128 SMs = 2 warps/SMSP.
    gru_fused_kernel<<<(B * 8) / BLK, BLK>>>(x, W_ih, W_hh, b_ih, b_hh, W_fc, b_fc, out);
}